// round 13
// baseline (speedup 1.0000x reference)
#include <cuda_runtime.h>
#include <cuda_fp16.h>
#include <cstdint>

// Problem constants
#define BATCH 16
#define TT    8192
#define HH    256
#define HQ    64
#define KSLOT 128
#define TILE  64                        // tokens per tile
#define NT64  (BATCH * (TT / TILE))     // 2048 tiles
#define NB1   (TT / 16)                 // 512 fine blocks (16 tokens)
#define NSB   (TT / 256)                // 32 superblocks
#define XROW  132                       // 32-bit words per fp16 tile row (264 halves)
#define XT_WORDS (TILE * XROW)          // 8448

// Scratch
__device__ float d_e [BATCH * TT];
__device__ float d_S [BATCH * NB1 * HH];
__device__ float d_E [BATCH * NB1];
__device__ float d_S2[BATCH * NSB * HH];
__device__ float d_E2[BATCH * NSB];

__device__ __forceinline__ float tanha(float x) {
    float r; asm("tanh.approx.f32 %0, %1;" : "=f"(r) : "f"(x)); return r;
}
__device__ __forceinline__ uint32_t h2u(__half2 h) {
    uint32_t u; *(__half2*)&u = h; return u;
}
#define MMA_F16(acc, a0, a1, a2, a3, b0, b1) \
    asm volatile( \
        "mma.sync.aligned.m16n8k16.row.col.f32.f16.f16.f32 " \
        "{%0,%1,%2,%3},{%4,%5,%6,%7},{%8,%9},{%0,%1,%2,%3};" \
        : "+f"((acc)[0]), "+f"((acc)[1]), "+f"((acc)[2]), "+f"((acc)[3]) \
        : "r"(a0), "r"(a1), "r"(a2), "r"(a3), "r"(b0), "r"(b1))

// smem (32-bit words): sX16[8448] | sP[64*4+16] | sE[64] | sB1[64] | sW2[64]
#define SMEM_A_WORDS (XT_WORDS + 64 * 4 + 16 + 64 + 64 + 64)
#define SMEM_A_BYTES (SMEM_A_WORDS * 4)

__global__ void __launch_bounds__(256, 2) pass_a_kernel(
    const float* __restrict__ x,
    const float* __restrict__ W1,
    const float* __restrict__ b1,
    const float* __restrict__ W2,
    const float* __restrict__ b2)
{
    extern __shared__ float sm[];
    uint32_t* sXw = (uint32_t*)sm;               // fp16 tile as 32-bit words
    float* sP  = sm + XT_WORDS;                  // [64][4] + pad
    float* sE  = sP + 64 * 4 + 16;
    float* sB1 = sE + 64;
    float* sW2 = sB1 + 64;

    const int tid  = threadIdx.x;
    const int warp = tid >> 5;           // 0..7
    const int lane = tid & 31;
    const int g    = lane >> 2;          // 0..7
    const int q    = lane & 3;           // 0..3
    const int th   = warp & 1;           // token half: rows [th*32, th*32+32)
    const int nq   = warp >> 1;          // n quarter: cols [nq*16, nq*16+16)
    const int r0   = th * 32;            // warp's token base

    uint32_t smem_u32;
    { uint64_t t64; asm("cvta.to.shared.u64 %0, %1;" : "=l"(t64) : "l"(sm));
      smem_u32 = (uint32_t)t64; }

    if (tid < 64) { sB1[tid] = b1[tid]; sW2[tid] = W2[tid]; }

    // --- W1 register-resident fp16 B frags: warp covers FULL K=256 x 16 n ---
    uint32_t Breg[16][2][2];
    #pragma unroll
    for (int kt = 0; kt < 16; kt++)
        #pragma unroll
        for (int nt = 0; nt < 2; nt++) {
            const int n  = nq * 16 + nt * 8 + g;
            const int k0 = kt * 16;
            Breg[kt][nt][0] = h2u(__floats2half2_rn(
                W1[(k0 + 2 * q)     * HQ + n], W1[(k0 + 2 * q + 1) * HQ + n]));
            Breg[kt][nt][1] = h2u(__floats2half2_rn(
                W1[(k0 + 2 * q + 8) * HQ + n], W1[(k0 + 2 * q + 9) * HQ + n]));
        }
    const float bb2 = b2[0];

    // ldmatrix bases (per m-tile): row r0 + m*16 + (lane&15), byte-col (lane&16)
    const uint32_t lm0 = smem_u32
        + (uint32_t)(r0 + (lane & 15)) * (XROW * 4u)
        + (uint32_t)(lane & 16);
    const uint32_t lm1 = lm0 + 16u * (XROW * 4u);

    // loader: 8 threads/token, two passes (tokens 0-31, 32-63)
    const int lt = tid >> 3;             // token within pass
    const int lj = tid & 7;

    // prefetch registers: fp16-converted, 2 passes x 8 chunks x 2 words
    uint32_t pf[2][8][2];
    int tile = blockIdx.x;
    {
        #pragma unroll
        for (int p = 0; p < 2; p++) {
            const float* src = x + (size_t)tile * (TILE * HH)
                             + (size_t)(p * 32 + lt) * HH + lj * 4;
            #pragma unroll
            for (int s = 0; s < 8; s++) {
                float4 v = *(const float4*)(src + 32 * s);
                pf[p][s][0] = h2u(__floats2half2_rn(v.x, v.y));
                pf[p][s][1] = h2u(__floats2half2_rn(v.z, v.w));
            }
        }
    }

    for (; tile < NT64; tile += gridDim.x) {
        const int next = tile + gridDim.x;

        __syncthreads();   // prev tile fully consumed

        // --- store held fp16 registers to tile ---
        #pragma unroll
        for (int p = 0; p < 2; p++) {
            const uint32_t stw0 = (uint32_t)((p * 32 + lt) * XROW + lj * 2);
            #pragma unroll
            for (int s = 0; s < 8; s++)
                asm volatile("st.shared.v2.b32 [%0], {%1, %2};"
                    :: "r"(smem_u32 + (stw0 + 16u * s) * 4),
                       "r"(pf[p][s][0]), "r"(pf[p][s][1]));
        }
        // --- prefetch next tile (overlaps compute) ---
        if (next < NT64) {
            #pragma unroll
            for (int p = 0; p < 2; p++) {
                const float* src = x + (size_t)next * (TILE * HH)
                                 + (size_t)(p * 32 + lt) * HH + lj * 4;
                #pragma unroll
                for (int s = 0; s < 8; s++) {
                    float4 v = *(const float4*)(src + 32 * s);
                    pf[p][s][0] = h2u(__floats2half2_rn(v.x, v.y));
                    pf[p][s][1] = h2u(__floats2half2_rn(v.z, v.w));
                }
            }
        }
        __syncthreads();   // tile visible

        // --- MMA: warp = 32 tokens x 16 n-cols x full K (32 LDSM + 64 HMMA) ---
        float acc[2][2][4];
        #pragma unroll
        for (int m = 0; m < 2; m++)
            #pragma unroll
            for (int nt = 0; nt < 2; nt++)
                #pragma unroll
                for (int i = 0; i < 4; i++) acc[m][nt][i] = 0.f;

        #pragma unroll
        for (int kt = 0; kt < 16; kt++) {
            const uint32_t koff = (uint32_t)(kt * 32);
            uint32_t a0, a1, a2, a3;
            asm volatile(
                "ldmatrix.sync.aligned.m8n8.x4.shared.b16 {%0,%1,%2,%3}, [%4];"
                : "=r"(a0), "=r"(a1), "=r"(a2), "=r"(a3)
                : "r"(lm0 + koff));
            #pragma unroll
            for (int nt = 0; nt < 2; nt++)
                MMA_F16(acc[0][nt], a0, a1, a2, a3,
                        Breg[kt][nt][0], Breg[kt][nt][1]);
            uint32_t c0, c1, c2, c3;
            asm volatile(
                "ldmatrix.sync.aligned.m8n8.x4.shared.b16 {%0,%1,%2,%3}, [%4];"
                : "=r"(c0), "=r"(c1), "=r"(c2), "=r"(c3)
                : "r"(lm1 + koff));
            #pragma unroll
            for (int nt = 0; nt < 2; nt++)
                MMA_F16(acc[1][nt], c0, c1, c2, c3,
                        Breg[kt][nt][0], Breg[kt][nt][1]);
        }

        // --- local epilogue: tanh + W2-dot over this warp's 16 cols ---
        #pragma unroll
        for (int m = 0; m < 2; m++) {
            float p0 = 0.f, p1 = 0.f;
            #pragma unroll
            for (int nt = 0; nt < 2; nt++) {
                const int c0 = nq * 16 + nt * 8 + 2 * q;
                const float w0 = sW2[c0], w1 = sW2[c0 + 1];
                const float bb0 = sB1[c0], bb1 = sB1[c0 + 1];
                p0 += tanha(acc[m][nt][0] + bb0) * w0
                    + tanha(acc[m][nt][1] + bb1) * w1;
                p1 += tanha(acc[m][nt][2] + bb0) * w0
                    + tanha(acc[m][nt][3] + bb1) * w1;
            }
            p0 += __shfl_xor_sync(0xffffffffu, p0, 1);
            p0 += __shfl_xor_sync(0xffffffffu, p0, 2);
            p1 += __shfl_xor_sync(0xffffffffu, p1, 1);
            p1 += __shfl_xor_sync(0xffffffffu, p1, 2);
            if (q == 0) {
                const int rr = r0 + m * 16 + g;
                sP[(rr)     * 4 + nq] = p0;
                sP[(rr + 8) * 4 + nq] = p1;
            }
        }
        __syncthreads();

        const int b     = tile >> 7;         // batch (TT/TILE = 128)
        const int blk64 = tile & 127;

        if (tid < TILE) {
            const float4 p4 = *(const float4*)&sP[tid * 4];
            const float s = bb2 + (p4.x + p4.y) + (p4.z + p4.w);
            const float e = __expf(s);
            sE[tid] = e;
            d_e[b * TT + blk64 * TILE + tid] = e;
            float d = e;
            d += __shfl_xor_sync(0xffffffffu, d, 1);
            d += __shfl_xor_sync(0xffffffffu, d, 2);
            d += __shfl_xor_sync(0xffffffffu, d, 4);
            d += __shfl_xor_sync(0xffffffffu, d, 8);
            if ((tid & 15) == 0)
                d_E[b * NB1 + blk64 * 4 + (tid >> 4)] = d;
        }
        __syncthreads();   // sE visible

        // --- blocksum: thread = (2 blocks, h-pair), half2 loads ---
        {
            const int jb = tid >> 7;         // handles blocks jb, jb+2
            const int hp = tid & 127;        // h pair index (h = 2*hp)
            #pragma unroll
            for (int jj = 0; jj < 2; jj++) {
                const int j = jb + jj * 2;
                float ax = 0.f, ay = 0.f;
                #pragma unroll
                for (int t = 0; t < 16; t++) {
                    const int tt = j * 16 + t;
                    const uint32_t v = sXw[tt * XROW + hp];
                    const float2 f = __half22float2(*(const __half2*)&v);
                    const float e = sE[tt];
                    ax += e * f.x; ay += e * f.y;
                }
                const int bi = b * NB1 + blk64 * 4 + j;
                *(float2*)&d_S[(size_t)bi * HH + 2 * hp] = make_float2(ax, ay);
            }
        }
    }
}

// Aggregate 16 fine blocks -> 1 superblock
__global__ void __launch_bounds__(256) pass_ab_kernel()
{
    const int sb  = blockIdx.x & (NSB - 1);
    const int b   = blockIdx.x >> 5;
    const int tid = threadIdx.x;

    const float* Sb = d_S + ((size_t)(b * NB1 + sb * 16)) * HH + tid;
    float s0 = 0.f, s1 = 0.f, s2 = 0.f, s3 = 0.f;
    #pragma unroll
    for (int i = 0; i < 16; i += 4) {
        s0 += Sb[(size_t)(i + 0) * HH];
        s1 += Sb[(size_t)(i + 1) * HH];
        s2 += Sb[(size_t)(i + 2) * HH];
        s3 += Sb[(size_t)(i + 3) * HH];
    }
    d_S2[(size_t)(b * NSB + sb) * HH + tid] = (s0 + s1) + (s2 + s3);
    if (tid == 0) {
        float e = 0.f;
        #pragma unroll
        for (int i = 0; i < 16; i++) e += d_E[b * NB1 + sb * 16 + i];
        d_E2[b * NSB + sb] = e;
    }
}

__global__ void __launch_bounds__(256) pass_b_kernel(
    const float* __restrict__ x,
    const int*   __restrict__ boundaries,
    const int*   __restrict__ slot_mask,
    float*       __restrict__ out)
{
    const int k   = blockIdx.x;
    const int b   = blockIdx.y;
    const int tid = threadIdx.x;     // h index

    const int sidx  = b * KSLOT + k;
    const int start = boundaries[sidx * 2];
    const int end   = boundaries[sidx * 2 + 1];
    const int mask  = slot_mask[sidx];

    float* o = out + (size_t)sidx * HH;
    if (mask <= 0 || start >= end) { o[tid] = 0.f; return; }

    const float* xb  = x    + (size_t)b * TT * HH;
    const float* eb  = d_e  + b * TT;
    const float* Sb1 = d_S  + (size_t)b * NB1 * HH;
    const float* Eb1 = d_E  + b * NB1;
    const float* Sb2 = d_S2 + (size_t)b * NSB * HH;
    const float* Eb2 = d_E2 + b * NSB;

    float acc = 0.f, den = 0.f;

    auto tokens = [&](int t0, int t1) {
        float ea = 0.f, ec = 0.f, da = 0.f, dc = 0.f;
        int t = t0;
        for (; t + 2 <= t1; t += 2) {
            const float e0 = eb[t], e1 = eb[t + 1];
            ea += e0 * xb[(size_t)(t)     * HH + tid]; da += e0;
            ec += e1 * xb[(size_t)(t + 1) * HH + tid]; dc += e1;
        }
        if (t < t1) { const float e = eb[t]; ea += e * xb[(size_t)t * HH + tid]; da += e; }
        acc += ea + ec; den += da + dc;
    };
    auto blocks = [&](int i0, int i1) {
        float a0 = 0.f, a1 = 0.f, d0 = 0.f, d1 = 0.f;
        int i = i0;
        for (; i + 2 <= i1; i += 2) {
            a0 += Sb1[(size_t)(i)     * HH + tid]; d0 += Eb1[i];
            a1 += Sb1[(size_t)(i + 1) * HH + tid]; d1 += Eb1[i + 1];
        }
        if (i < i1) { a0 += Sb1[(size_t)i * HH + tid]; d0 += Eb1[i]; }
        acc += a0 + a1; den += d0 + d1;
    };

    const int fb = (start + 15) >> 4;
    const int lb = end >> 4;

    if (fb >= lb) {
        tokens(start, end);
    } else {
        tokens(start, fb * 16);
        tokens(lb * 16, end);

        const int fs = (fb + 15) >> 4;
        const int ls = lb >> 4;
        if (fs >= ls) {
            blocks(fb, lb);
        } else {
            blocks(fb, fs * 16);
            blocks(ls * 16, lb);
            float a0 = 0.f, a1 = 0.f, a2 = 0.f, a3 = 0.f;
            float d0 = 0.f, d1 = 0.f, d2 = 0.f, d3 = 0.f;
            int i = fs;
            for (; i + 4 <= ls; i += 4) {
                a0 += Sb2[(size_t)(i + 0) * HH + tid]; d0 += Eb2[i + 0];
                a1 += Sb2[(size_t)(i + 1) * HH + tid]; d1 += Eb2[i + 1];
                a2 += Sb2[(size_t)(i + 2) * HH + tid]; d2 += Eb2[i + 2];
                a3 += Sb2[(size_t)(i + 3) * HH + tid]; d3 += Eb2[i + 3];
            }
            for (; i < ls; i++) { a0 += Sb2[(size_t)i * HH + tid]; d0 += Eb2[i]; }
            acc += (a0 + a1) + (a2 + a3);
            den += (d0 + d1) + (d2 + d3);
        }
    }

    o[tid] = acc / den;   // den > 0: end > start and all e_t > 0
}

extern "C" void kernel_launch(void* const* d_in, const int* in_sizes, int n_in,
                              void* d_out, int out_size)
{
    const float* x          = (const float*)d_in[0];
    const int*   boundaries = (const int*)d_in[1];
    const int*   slot_mask  = (const int*)d_in[2];
    const float* W1         = (const float*)d_in[3];
    const float* b1         = (const float*)d_in[4];
    const float* W2         = (const float*)d_in[5];
    const float* b2         = (const float*)d_in[6];
    float* out = (float*)d_out;

    cudaFuncSetAttribute(pass_a_kernel,
                         cudaFuncAttributeMaxDynamicSharedMemorySize,
                         SMEM_A_BYTES);

    pass_a_kernel<<<296, 256, SMEM_A_BYTES>>>(x, W1, b1, W2, b2);
    pass_ab_kernel<<<BATCH * NSB, 256>>>();
    pass_b_kernel<<<dim3(KSLOT, BATCH), 256>>>(x, boundaries, slot_mask, out);
}

// round 14
// speedup vs baseline: 1.0407x; 1.0407x over previous
#include <cuda_runtime.h>
#include <cuda_fp16.h>
#include <cstdint>

// Problem constants
#define BATCH 16
#define TT    8192
#define HH    256
#define HQ    64
#define KSLOT 128
#define TILE  32                        // tokens per tile
#define NT32  (BATCH * (TT / TILE))     // 4096 tiles
#define NB1   (TT / 16)                 // 512 fine blocks (16 tokens)
#define NSB   (TT / 256)                // 32 superblocks
#define XROW  132                       // 32-bit words per fp16 tile row (264 halves)
#define XT_WORDS (TILE * XROW)          // 4224

// Scratch
__device__ float d_e [BATCH * TT];
__device__ float d_S [BATCH * NB1 * HH];
__device__ float d_E [BATCH * NB1];
__device__ float d_S2[BATCH * NSB * HH];
__device__ float d_E2[BATCH * NSB];

__device__ __forceinline__ float tanha(float x) {
    float r; asm("tanh.approx.f32 %0, %1;" : "=f"(r) : "f"(x)); return r;
}
__device__ __forceinline__ uint32_t h2u(__half2 h) {
    uint32_t u; *(__half2*)&u = h; return u;
}
#define MMA_F16(acc, a0, a1, a2, a3, b0, b1) \
    asm volatile( \
        "mma.sync.aligned.m16n8k16.row.col.f32.f16.f16.f32 " \
        "{%0,%1,%2,%3},{%4,%5,%6,%7},{%8,%9},{%0,%1,%2,%3};" \
        : "+f"((acc)[0]), "+f"((acc)[1]), "+f"((acc)[2]), "+f"((acc)[3]) \
        : "r"(a0), "r"(a1), "r"(a2), "r"(a3), "r"(b0), "r"(b1))

// smem (32-bit words): sX16[4224] | sP[32*4+16] | sE[32] | sB1[64] | sW2[64]
#define SMEM_A_WORDS (XT_WORDS + 32 * 4 + 16 + 32 + 64 + 64)
#define SMEM_A_BYTES (SMEM_A_WORDS * 4)

__global__ void __launch_bounds__(256, 2) pass_a_kernel(
    const float* __restrict__ x,
    const float* __restrict__ W1,
    const float* __restrict__ b1,
    const float* __restrict__ W2,
    const float* __restrict__ b2)
{
    extern __shared__ float sm[];
    uint32_t* sXw = (uint32_t*)sm;               // fp16 tile as 32-bit words
    float* sP  = sm + XT_WORDS;                  // [32][4] + pad
    float* sE  = sP + 32 * 4 + 16;
    float* sB1 = sE + 32;
    float* sW2 = sB1 + 64;

    const int tid  = threadIdx.x;
    const int warp = tid >> 5;           // 0..7
    const int lane = tid & 31;
    const int g    = lane >> 2;          // 0..7
    const int q    = lane & 3;           // 0..3
    const int th   = warp & 1;           // token half: rows [th*16, th*16+16)
    const int nq   = warp >> 1;          // n quarter: cols [nq*16, nq*16+16)
    const int r0   = th * 16;            // warp's token base

    uint32_t smem_u32;
    { uint64_t t64; asm("cvta.to.shared.u64 %0, %1;" : "=l"(t64) : "l"(sm));
      smem_u32 = (uint32_t)t64; }

    if (tid < 64) { sB1[tid] = b1[tid]; sW2[tid] = W2[tid]; }

    // --- W1 register-resident fp16 B frags: warp covers FULL K=256 x 16 n ---
    uint32_t Breg[16][2][2];
    #pragma unroll
    for (int kt = 0; kt < 16; kt++)
        #pragma unroll
        for (int nt = 0; nt < 2; nt++) {
            const int n  = nq * 16 + nt * 8 + g;
            const int k0 = kt * 16;
            Breg[kt][nt][0] = h2u(__floats2half2_rn(
                W1[(k0 + 2 * q)     * HQ + n], W1[(k0 + 2 * q + 1) * HQ + n]));
            Breg[kt][nt][1] = h2u(__floats2half2_rn(
                W1[(k0 + 2 * q + 8) * HQ + n], W1[(k0 + 2 * q + 9) * HQ + n]));
        }
    const float bb2 = b2[0];

    // ldmatrix base: lane -> row r0+(lane&15), byte-col (lane&16)
    const uint32_t lmbase = smem_u32
        + (uint32_t)(r0 + (lane & 15)) * (XROW * 4u)
        + (uint32_t)(lane & 16);

    // loader mapping: thread -> (token t = tid>>3, h = (tid&7)*4 + 32*s)
    const int lt = tid >> 3;
    const int lj = tid & 7;
    const uint32_t stw0 = (uint32_t)(lt * XROW + lj * 2);

    // prefetch registers: fp16-converted, 8 chunks x 2 words (16 regs)
    uint32_t pf[8][2];
    int tile = blockIdx.x;
    {   // prefetch first tile
        const float* src = x + (size_t)tile * (TILE * HH) + (size_t)lt * HH + lj * 4;
        #pragma unroll
        for (int s = 0; s < 8; s++) {
            float4 v = *(const float4*)(src + 32 * s);
            pf[s][0] = h2u(__floats2half2_rn(v.x, v.y));
            pf[s][1] = h2u(__floats2half2_rn(v.z, v.w));
        }
    }

    for (; tile < NT32; tile += gridDim.x) {
        const int next = tile + gridDim.x;

        __syncthreads();   // prev tile fully consumed

        // --- store held fp16 registers to tile ---
        #pragma unroll
        for (int s = 0; s < 8; s++)
            asm volatile("st.shared.v2.b32 [%0], {%1, %2};"
                :: "r"(smem_u32 + (stw0 + 16u * s) * 4),
                   "r"(pf[s][0]), "r"(pf[s][1]));
        // --- prefetch next tile (overlaps compute) ---
        if (next < NT32) {
            const float* src = x + (size_t)next * (TILE * HH) + (size_t)lt * HH + lj * 4;
            #pragma unroll
            for (int s = 0; s < 8; s++) {
                float4 v = *(const float4*)(src + 32 * s);
                pf[s][0] = h2u(__floats2half2_rn(v.x, v.y));
                pf[s][1] = h2u(__floats2half2_rn(v.z, v.w));
            }
        }
        __syncthreads();   // tile visible

        // --- MMA: warp = 16 tokens x 16 n-cols x full K (16 LDSM + 32 HMMA) ---
        float acc[2][4];
        #pragma unroll
        for (int nt = 0; nt < 2; nt++)
            #pragma unroll
            for (int i = 0; i < 4; i++) acc[nt][i] = 0.f;

        #pragma unroll
        for (int kt = 0; kt < 16; kt++) {
            uint32_t a0, a1, a2, a3;
            asm volatile(
                "ldmatrix.sync.aligned.m8n8.x4.shared.b16 {%0,%1,%2,%3}, [%4];"
                : "=r"(a0), "=r"(a1), "=r"(a2), "=r"(a3)
                : "r"(lmbase + (uint32_t)(kt * 32)));
            #pragma unroll
            for (int nt = 0; nt < 2; nt++)
                MMA_F16(acc[nt], a0, a1, a2, a3,
                        Breg[kt][nt][0], Breg[kt][nt][1]);
        }

        // --- local epilogue: tanh + W2-dot over this warp's 16 cols ---
        {
            float p0 = 0.f, p1 = 0.f;
            #pragma unroll
            for (int nt = 0; nt < 2; nt++) {
                const int c0 = nq * 16 + nt * 8 + 2 * q;
                const float w0 = sW2[c0], w1 = sW2[c0 + 1];
                const float bb0 = sB1[c0], bb1 = sB1[c0 + 1];
                p0 += tanha(acc[nt][0] + bb0) * w0
                    + tanha(acc[nt][1] + bb1) * w1;
                p1 += tanha(acc[nt][2] + bb0) * w0
                    + tanha(acc[nt][3] + bb1) * w1;
            }
            p0 += __shfl_xor_sync(0xffffffffu, p0, 1);
            p0 += __shfl_xor_sync(0xffffffffu, p0, 2);
            p1 += __shfl_xor_sync(0xffffffffu, p1, 1);
            p1 += __shfl_xor_sync(0xffffffffu, p1, 2);
            if (q == 0) {
                sP[(r0 + g)     * 4 + nq] = p0;
                sP[(r0 + g + 8) * 4 + nq] = p1;
            }
        }
        __syncthreads();

        const int b     = tile >> 8;         // batch (TT/TILE = 256)
        const int blk32 = tile & 255;

        if (tid < TILE) {
            const float4 p4 = *(const float4*)&sP[tid * 4];
            const float s = bb2 + (p4.x + p4.y) + (p4.z + p4.w);
            const float e = __expf(s);
            sE[tid] = e;
            d_e[b * TT + blk32 * TILE + tid] = e;
            float d = e;
            d += __shfl_xor_sync(0xffffffffu, d, 1);
            d += __shfl_xor_sync(0xffffffffu, d, 2);
            d += __shfl_xor_sync(0xffffffffu, d, 4);
            d += __shfl_xor_sync(0xffffffffu, d, 8);
            if ((tid & 15) == 0)
                d_E[b * NB1 + blk32 * 2 + (tid >> 4)] = d;
        }
        __syncthreads();   // sE visible

        // --- blocksum: thread = (block j, h-pair), half2 loads ---
        {
            const int jb = tid >> 7;         // 0,1 -> 16-token block
            const int hp = tid & 127;        // h pair index (h = 2*hp)
            float ax = 0.f, ay = 0.f;
            #pragma unroll
            for (int t = 0; t < 16; t++) {
                const int tt = jb * 16 + t;
                const uint32_t v = sXw[tt * XROW + hp];
                const float2 f = __half22float2(*(const __half2*)&v);
                const float e = sE[tt];
                ax += e * f.x; ay += e * f.y;
            }
            const int bi = b * NB1 + blk32 * 2 + jb;
            *(float2*)&d_S[(size_t)bi * HH + 2 * hp] = make_float2(ax, ay);
        }
    }
}

// Aggregate 16 fine blocks -> 1 superblock
__global__ void __launch_bounds__(256) pass_ab_kernel()
{
    const int sb  = blockIdx.x & (NSB - 1);
    const int b   = blockIdx.x >> 5;
    const int tid = threadIdx.x;

    const float* Sb = d_S + ((size_t)(b * NB1 + sb * 16)) * HH + tid;
    float s0 = 0.f, s1 = 0.f, s2 = 0.f, s3 = 0.f;
    #pragma unroll
    for (int i = 0; i < 16; i += 4) {
        s0 += Sb[(size_t)(i + 0) * HH];
        s1 += Sb[(size_t)(i + 1) * HH];
        s2 += Sb[(size_t)(i + 2) * HH];
        s3 += Sb[(size_t)(i + 3) * HH];
    }
    d_S2[(size_t)(b * NSB + sb) * HH + tid] = (s0 + s1) + (s2 + s3);
    if (tid == 0) {
        float e = 0.f;
        #pragma unroll
        for (int i = 0; i < 16; i++) e += d_E[b * NB1 + sb * 16 + i];
        d_E2[b * NSB + sb] = e;
    }
}

__global__ void __launch_bounds__(256) pass_b_kernel(
    const float* __restrict__ x,
    const int*   __restrict__ boundaries,
    const int*   __restrict__ slot_mask,
    float*       __restrict__ out)
{
    const int k   = blockIdx.x;
    const int b   = blockIdx.y;
    const int tid = threadIdx.x;     // h index

    const int sidx  = b * KSLOT + k;
    const int start = boundaries[sidx * 2];
    const int end   = boundaries[sidx * 2 + 1];
    const int mask  = slot_mask[sidx];

    float* o = out + (size_t)sidx * HH;
    if (mask <= 0 || start >= end) { o[tid] = 0.f; return; }

    const float* xb  = x    + (size_t)b * TT * HH;
    const float* eb  = d_e  + b * TT;
    const float* Sb1 = d_S  + (size_t)b * NB1 * HH;
    const float* Eb1 = d_E  + b * NB1;
    const float* Sb2 = d_S2 + (size_t)b * NSB * HH;
    const float* Eb2 = d_E2 + b * NSB;

    float acc = 0.f, den = 0.f;

    auto tokens = [&](int t0, int t1) {
        float ea = 0.f, ec = 0.f, da = 0.f, dc = 0.f;
        int t = t0;
        for (; t + 2 <= t1; t += 2) {
            const float e0 = eb[t], e1 = eb[t + 1];
            ea += e0 * xb[(size_t)(t)     * HH + tid]; da += e0;
            ec += e1 * xb[(size_t)(t + 1) * HH + tid]; dc += e1;
        }
        if (t < t1) { const float e = eb[t]; ea += e * xb[(size_t)t * HH + tid]; da += e; }
        acc += ea + ec; den += da + dc;
    };
    auto blocks = [&](int i0, int i1) {
        float a0 = 0.f, a1 = 0.f, d0 = 0.f, d1 = 0.f;
        int i = i0;
        for (; i + 2 <= i1; i += 2) {
            a0 += Sb1[(size_t)(i)     * HH + tid]; d0 += Eb1[i];
            a1 += Sb1[(size_t)(i + 1) * HH + tid]; d1 += Eb1[i + 1];
        }
        if (i < i1) { a0 += Sb1[(size_t)i * HH + tid]; d0 += Eb1[i]; }
        acc += a0 + a1; den += d0 + d1;
    };

    const int fb = (start + 15) >> 4;
    const int lb = end >> 4;

    if (fb >= lb) {
        tokens(start, end);
    } else {
        tokens(start, fb * 16);
        tokens(lb * 16, end);

        const int fs = (fb + 15) >> 4;
        const int ls = lb >> 4;
        if (fs >= ls) {
            blocks(fb, lb);
        } else {
            blocks(fb, fs * 16);
            blocks(ls * 16, lb);
            float a0 = 0.f, a1 = 0.f, a2 = 0.f, a3 = 0.f;
            float d0 = 0.f, d1 = 0.f, d2 = 0.f, d3 = 0.f;
            int i = fs;
            for (; i + 4 <= ls; i += 4) {
                a0 += Sb2[(size_t)(i + 0) * HH + tid]; d0 += Eb2[i + 0];
                a1 += Sb2[(size_t)(i + 1) * HH + tid]; d1 += Eb2[i + 1];
                a2 += Sb2[(size_t)(i + 2) * HH + tid]; d2 += Eb2[i + 2];
                a3 += Sb2[(size_t)(i + 3) * HH + tid]; d3 += Eb2[i + 3];
            }
            for (; i < ls; i++) { a0 += Sb2[(size_t)i * HH + tid]; d0 += Eb2[i]; }
            acc += (a0 + a1) + (a2 + a3);
            den += (d0 + d1) + (d2 + d3);
        }
    }

    o[tid] = acc / den;   // den > 0: end > start and all e_t > 0
}

extern "C" void kernel_launch(void* const* d_in, const int* in_sizes, int n_in,
                              void* d_out, int out_size)
{
    const float* x          = (const float*)d_in[0];
    const int*   boundaries = (const int*)d_in[1];
    const int*   slot_mask  = (const int*)d_in[2];
    const float* W1         = (const float*)d_in[3];
    const float* b1         = (const float*)d_in[4];
    const float* W2         = (const float*)d_in[5];
    const float* b2         = (const float*)d_in[6];
    float* out = (float*)d_out;

    cudaFuncSetAttribute(pass_a_kernel,
                         cudaFuncAttributeMaxDynamicSharedMemorySize,
                         SMEM_A_BYTES);

    pass_a_kernel<<<296, 256, SMEM_A_BYTES>>>(x, W1, b1, W2, b2);
    pass_ab_kernel<<<BATCH * NSB, 256>>>();
    pass_b_kernel<<<dim3(KSLOT, BATCH), 256>>>(x, boundaries, slot_mask, out);
}

// round 15
// speedup vs baseline: 1.1702x; 1.1244x over previous
#include <cuda_runtime.h>
#include <cuda_fp16.h>
#include <cstdint>

// Problem constants
#define BATCH 16
#define TT    8192
#define HH    256
#define HQ    64
#define KSLOT 128
#define TILE  32                        // tokens per tile
#define NT32  (BATCH * (TT / TILE))     // 4096 tiles
#define NB1   (TT / 16)                 // 512 fine blocks (16 tokens)
#define NM    (TT / 64)                 // 128 mid blocks (64 tokens)
#define NSB   (TT / 256)                // 32 superblocks (256 tokens)
#define XROW  132                       // 32-bit words per fp16 tile row (264 halves)
#define XT_WORDS (TILE * XROW)          // 4224

// Scratch
__device__ float d_e [BATCH * TT];
__device__ float d_S [BATCH * NB1 * HH];
__device__ float d_E [BATCH * NB1];
__device__ float d_SM[BATCH * NM * HH];
__device__ float d_EM[BATCH * NM];
__device__ float d_S2[BATCH * NSB * HH];
__device__ float d_E2[BATCH * NSB];

__device__ __forceinline__ float tanha(float x) {
    float r; asm("tanh.approx.f32 %0, %1;" : "=f"(r) : "f"(x)); return r;
}
__device__ __forceinline__ uint32_t h2u(__half2 h) {
    uint32_t u; *(__half2*)&u = h; return u;
}
#define MMA_F16(acc, a0, a1, a2, a3, b0, b1) \
    asm volatile( \
        "mma.sync.aligned.m16n8k16.row.col.f32.f16.f16.f32 " \
        "{%0,%1,%2,%3},{%4,%5,%6,%7},{%8,%9},{%0,%1,%2,%3};" \
        : "+f"((acc)[0]), "+f"((acc)[1]), "+f"((acc)[2]), "+f"((acc)[3]) \
        : "r"(a0), "r"(a1), "r"(a2), "r"(a3), "r"(b0), "r"(b1))

// smem (32-bit words): sX16[4224] | sP[32*4+16] | sE[32] | sB1[64] | sW2[64]
#define SMEM_A_WORDS (XT_WORDS + 32 * 4 + 16 + 32 + 64 + 64)
#define SMEM_A_BYTES (SMEM_A_WORDS * 4)

__global__ void __launch_bounds__(256, 2) pass_a_kernel(
    const float* __restrict__ x,
    const float* __restrict__ W1,
    const float* __restrict__ b1,
    const float* __restrict__ W2,
    const float* __restrict__ b2)
{
    extern __shared__ float sm[];
    uint32_t* sXw = (uint32_t*)sm;               // fp16 tile as 32-bit words
    float* sP  = sm + XT_WORDS;                  // [32][4] + pad
    float* sE  = sP + 32 * 4 + 16;
    float* sB1 = sE + 32;
    float* sW2 = sB1 + 64;

    const int tid  = threadIdx.x;
    const int warp = tid >> 5;           // 0..7
    const int lane = tid & 31;
    const int g    = lane >> 2;          // 0..7
    const int q    = lane & 3;           // 0..3
    const int th   = warp & 1;           // token half: rows [th*16, th*16+16)
    const int nq   = warp >> 1;          // n quarter: cols [nq*16, nq*16+16)
    const int r0   = th * 16;            // warp's token base

    uint32_t smem_u32;
    { uint64_t t64; asm("cvta.to.shared.u64 %0, %1;" : "=l"(t64) : "l"(sm));
      smem_u32 = (uint32_t)t64; }

    if (tid < 64) { sB1[tid] = b1[tid]; sW2[tid] = W2[tid]; }

    // --- W1 register-resident fp16 B frags: warp covers FULL K=256 x 16 n ---
    uint32_t Breg[16][2][2];
    #pragma unroll
    for (int kt = 0; kt < 16; kt++)
        #pragma unroll
        for (int nt = 0; nt < 2; nt++) {
            const int n  = nq * 16 + nt * 8 + g;
            const int k0 = kt * 16;
            Breg[kt][nt][0] = h2u(__floats2half2_rn(
                W1[(k0 + 2 * q)     * HQ + n], W1[(k0 + 2 * q + 1) * HQ + n]));
            Breg[kt][nt][1] = h2u(__floats2half2_rn(
                W1[(k0 + 2 * q + 8) * HQ + n], W1[(k0 + 2 * q + 9) * HQ + n]));
        }
    const float bb2 = b2[0];

    // ldmatrix base: lane -> row r0+(lane&15), byte-col (lane&16)
    const uint32_t lmbase = smem_u32
        + (uint32_t)(r0 + (lane & 15)) * (XROW * 4u)
        + (uint32_t)(lane & 16);

    // loader mapping: thread -> (token t = tid>>3, h = (tid&7)*4 + 32*s)
    const int lt = tid >> 3;
    const int lj = tid & 7;
    const uint32_t stw0 = (uint32_t)(lt * XROW + lj * 2);

    float4 pf[8];
    int tile = blockIdx.x;
    {   // prefetch first tile into registers (raw fp32, max MLP)
        const float* src = x + (size_t)tile * (TILE * HH) + (size_t)lt * HH + lj * 4;
        #pragma unroll
        for (int s = 0; s < 8; s++) pf[s] = *(const float4*)(src + 32 * s);
    }

    for (; tile < NT32; tile += gridDim.x) {
        const int next = tile + gridDim.x;

        __syncthreads();   // prev tile fully consumed

        // --- store held registers as fp16 tile (convert at store) ---
        #pragma unroll
        for (int s = 0; s < 8; s++) {
            const uint32_t u0 = h2u(__floats2half2_rn(pf[s].x, pf[s].y));
            const uint32_t u1 = h2u(__floats2half2_rn(pf[s].z, pf[s].w));
            asm volatile("st.shared.v2.b32 [%0], {%1, %2};"
                :: "r"(smem_u32 + (stw0 + 16u * s) * 4), "r"(u0), "r"(u1));
        }
        // --- prefetch next tile (overlaps compute) ---
        if (next < NT32) {
            const float* src = x + (size_t)next * (TILE * HH) + (size_t)lt * HH + lj * 4;
            #pragma unroll
            for (int s = 0; s < 8; s++) pf[s] = *(const float4*)(src + 32 * s);
        }
        __syncthreads();   // tile visible

        // --- MMA: warp = 16 tokens x 16 n-cols x full K (16 LDSM + 32 HMMA) ---
        float acc[2][4];
        #pragma unroll
        for (int nt = 0; nt < 2; nt++)
            #pragma unroll
            for (int i = 0; i < 4; i++) acc[nt][i] = 0.f;

        #pragma unroll
        for (int kt = 0; kt < 16; kt++) {
            uint32_t a0, a1, a2, a3;
            asm volatile(
                "ldmatrix.sync.aligned.m8n8.x4.shared.b16 {%0,%1,%2,%3}, [%4];"
                : "=r"(a0), "=r"(a1), "=r"(a2), "=r"(a3)
                : "r"(lmbase + (uint32_t)(kt * 32)));
            #pragma unroll
            for (int nt = 0; nt < 2; nt++)
                MMA_F16(acc[nt], a0, a1, a2, a3,
                        Breg[kt][nt][0], Breg[kt][nt][1]);
        }

        // --- local epilogue: tanh + W2-dot over this warp's 16 cols ---
        {
            float p0 = 0.f, p1 = 0.f;
            #pragma unroll
            for (int nt = 0; nt < 2; nt++) {
                const int c0 = nq * 16 + nt * 8 + 2 * q;
                const float w0 = sW2[c0], w1 = sW2[c0 + 1];
                const float bb0 = sB1[c0], bb1 = sB1[c0 + 1];
                p0 += tanha(acc[nt][0] + bb0) * w0
                    + tanha(acc[nt][1] + bb1) * w1;
                p1 += tanha(acc[nt][2] + bb0) * w0
                    + tanha(acc[nt][3] + bb1) * w1;
            }
            p0 += __shfl_xor_sync(0xffffffffu, p0, 1);
            p0 += __shfl_xor_sync(0xffffffffu, p0, 2);
            p1 += __shfl_xor_sync(0xffffffffu, p1, 1);
            p1 += __shfl_xor_sync(0xffffffffu, p1, 2);
            if (q == 0) {
                sP[(r0 + g)     * 4 + nq] = p0;
                sP[(r0 + g + 8) * 4 + nq] = p1;
            }
        }
        __syncthreads();

        const int b     = tile >> 8;         // batch (TT/TILE = 256)
        const int blk32 = tile & 255;

        if (tid < TILE) {
            const float4 p4 = *(const float4*)&sP[tid * 4];
            const float s = bb2 + (p4.x + p4.y) + (p4.z + p4.w);
            const float e = __expf(s);
            sE[tid] = e;
            d_e[b * TT + blk32 * TILE + tid] = e;
            float d = e;
            d += __shfl_xor_sync(0xffffffffu, d, 1);
            d += __shfl_xor_sync(0xffffffffu, d, 2);
            d += __shfl_xor_sync(0xffffffffu, d, 4);
            d += __shfl_xor_sync(0xffffffffu, d, 8);
            if ((tid & 15) == 0)
                d_E[b * NB1 + blk32 * 2 + (tid >> 4)] = d;
        }
        __syncthreads();   // sE visible

        // --- blocksum: thread = (block j, h-pair), half2 loads ---
        {
            const int jb = tid >> 7;         // 0,1 -> 16-token block
            const int hp = tid & 127;        // h pair index (h = 2*hp)
            float ax = 0.f, ay = 0.f;
            #pragma unroll
            for (int t = 0; t < 16; t++) {
                const int tt = jb * 16 + t;
                const uint32_t v = sXw[tt * XROW + hp];
                const float2 f = __half22float2(*(const __half2*)&v);
                const float e = sE[tt];
                ax += e * f.x; ay += e * f.y;
            }
            const int bi = b * NB1 + blk32 * 2 + jb;
            *(float2*)&d_S[(size_t)bi * HH + 2 * hp] = make_float2(ax, ay);
        }
    }
}

// Aggregate 16 fine blocks -> 4 mid (64-token) + 1 super (256-token)
__global__ void __launch_bounds__(256) pass_ab_kernel()
{
    const int sb  = blockIdx.x & (NSB - 1);
    const int b   = blockIdx.x >> 5;
    const int tid = threadIdx.x;

    const float* Sb = d_S + ((size_t)(b * NB1 + sb * 16)) * HH + tid;
    float mg[4];
    #pragma unroll
    for (int gi = 0; gi < 4; gi++) {
        float s0 = Sb[(size_t)(gi * 4 + 0) * HH];
        float s1 = Sb[(size_t)(gi * 4 + 1) * HH];
        float s2 = Sb[(size_t)(gi * 4 + 2) * HH];
        float s3 = Sb[(size_t)(gi * 4 + 3) * HH];
        mg[gi] = (s0 + s1) + (s2 + s3);
        d_SM[(size_t)(b * NM + sb * 4 + gi) * HH + tid] = mg[gi];
    }
    d_S2[(size_t)(b * NSB + sb) * HH + tid] = (mg[0] + mg[1]) + (mg[2] + mg[3]);
    if (tid < 4) {
        float e = 0.f;
        #pragma unroll
        for (int i = 0; i < 4; i++) e += d_E[b * NB1 + sb * 16 + tid * 4 + i];
        d_EM[b * NM + sb * 4 + tid] = e;
        // warp-local sum of the 4 mid e's -> super e
        float t0 = __shfl_sync(0xfu, e, 0);
        float t1 = __shfl_sync(0xfu, e, 1);
        float t2 = __shfl_sync(0xfu, e, 2);
        float t3 = __shfl_sync(0xfu, e, 3);
        if (tid == 0) d_E2[b * NSB + sb] = (t0 + t1) + (t2 + t3);
    }
}

__global__ void __launch_bounds__(256) pass_b_kernel(
    const float* __restrict__ x,
    const int*   __restrict__ boundaries,
    const int*   __restrict__ slot_mask,
    float*       __restrict__ out)
{
    const int k   = blockIdx.x;
    const int b   = blockIdx.y;
    const int tid = threadIdx.x;     // h index

    const int sidx  = b * KSLOT + k;
    const int start = boundaries[sidx * 2];
    const int end   = boundaries[sidx * 2 + 1];
    const int mask  = slot_mask[sidx];

    float* o = out + (size_t)sidx * HH;
    if (mask <= 0 || start >= end) { o[tid] = 0.f; return; }

    const float* xb  = x    + (size_t)b * TT * HH;
    const float* eb  = d_e  + b * TT;
    const float* Sb1 = d_S  + (size_t)b * NB1 * HH;
    const float* Eb1 = d_E  + b * NB1;
    const float* SbM = d_SM + (size_t)b * NM * HH;
    const float* EbM = d_EM + b * NM;
    const float* Sb2 = d_S2 + (size_t)b * NSB * HH;
    const float* Eb2 = d_E2 + b * NSB;

    float acc = 0.f, den = 0.f;

    auto tokens = [&](int t0, int t1) {
        float ea = 0.f, ec = 0.f, da = 0.f, dc = 0.f;
        int t = t0;
        for (; t + 2 <= t1; t += 2) {
            const float e0 = eb[t], e1 = eb[t + 1];
            ea += e0 * xb[(size_t)(t)     * HH + tid]; da += e0;
            ec += e1 * xb[(size_t)(t + 1) * HH + tid]; dc += e1;
        }
        if (t < t1) { const float e = eb[t]; ea += e * xb[(size_t)t * HH + tid]; da += e; }
        acc += ea + ec; den += da + dc;
    };
    auto fine = [&](int i0, int i1) {
        float a0 = 0.f, a1 = 0.f, d0 = 0.f, d1 = 0.f;
        int i = i0;
        for (; i + 2 <= i1; i += 2) {
            a0 += Sb1[(size_t)(i)     * HH + tid]; d0 += Eb1[i];
            a1 += Sb1[(size_t)(i + 1) * HH + tid]; d1 += Eb1[i + 1];
        }
        if (i < i1) { a0 += Sb1[(size_t)i * HH + tid]; d0 += Eb1[i]; }
        acc += a0 + a1; den += d0 + d1;
    };
    auto mid = [&](int i0, int i1) {
        float a0 = 0.f, a1 = 0.f, d0 = 0.f, d1 = 0.f;
        int i = i0;
        for (; i + 2 <= i1; i += 2) {
            a0 += SbM[(size_t)(i)     * HH + tid]; d0 += EbM[i];
            a1 += SbM[(size_t)(i + 1) * HH + tid]; d1 += EbM[i + 1];
        }
        if (i < i1) { a0 += SbM[(size_t)i * HH + tid]; d0 += EbM[i]; }
        acc += a0 + a1; den += d0 + d1;
    };

    const int fb = (start + 15) >> 4;    // fine range [fb, lb)
    const int lb = end >> 4;

    if (fb >= lb) {
        tokens(start, end);
    } else {
        tokens(start, fb * 16);
        tokens(lb * 16, end);

        const int fm = (fb + 3) >> 2;    // mid range [fm, lm) (64-token units)
        const int lm = lb >> 2;
        if (fm >= lm) {
            fine(fb, lb);
        } else {
            fine(fb, fm * 4);
            fine(lm * 4, lb);

            const int fs = (fm + 3) >> 2;  // super range [fs, ls)
            const int ls = lm >> 2;
            if (fs >= ls) {
                mid(fm, lm);
            } else {
                mid(fm, fs * 4);
                mid(ls * 4, lm);
                float a0 = 0.f, a1 = 0.f, a2 = 0.f, a3 = 0.f;
                float d0 = 0.f, d1 = 0.f, d2 = 0.f, d3 = 0.f;
                int i = fs;
                for (; i + 4 <= ls; i += 4) {
                    a0 += Sb2[(size_t)(i + 0) * HH + tid]; d0 += Eb2[i + 0];
                    a1 += Sb2[(size_t)(i + 1) * HH + tid]; d1 += Eb2[i + 1];
                    a2 += Sb2[(size_t)(i + 2) * HH + tid]; d2 += Eb2[i + 2];
                    a3 += Sb2[(size_t)(i + 3) * HH + tid]; d3 += Eb2[i + 3];
                }
                for (; i < ls; i++) { a0 += Sb2[(size_t)i * HH + tid]; d0 += Eb2[i]; }
                acc += (a0 + a1) + (a2 + a3);
                den += (d0 + d1) + (d2 + d3);
            }
        }
    }

    o[tid] = acc / den;   // den > 0: end > start and all e_t > 0
}

extern "C" void kernel_launch(void* const* d_in, const int* in_sizes, int n_in,
                              void* d_out, int out_size)
{
    const float* x          = (const float*)d_in[0];
    const int*   boundaries = (const int*)d_in[1];
    const int*   slot_mask  = (const int*)d_in[2];
    const float* W1         = (const float*)d_in[3];
    const float* b1         = (const float*)d_in[4];
    const float* W2         = (const float*)d_in[5];
    const float* b2         = (const float*)d_in[6];
    float* out = (float*)d_out;

    cudaFuncSetAttribute(pass_a_kernel,
                         cudaFuncAttributeMaxDynamicSharedMemorySize,
                         SMEM_A_BYTES);

    pass_a_kernel<<<296, 256, SMEM_A_BYTES>>>(x, W1, b1, W2, b2);
    pass_ab_kernel<<<BATCH * NSB, 256>>>();
    pass_b_kernel<<<dim3(KSLOT, BATCH), 256>>>(x, boundaries, slot_mask, out);
}